// round 15
// baseline (speedup 1.0000x reference)
#include <cuda_runtime.h>
#include <stdint.h>

// out[b,t,n,f] = in[b,t,n,f] * ((n < set_size[b,t]) ? (ALPHA+BETA) : 0)
// B=32, T=64, N=128, F=256, fp32.
//
// FINAL. Best measured 63.68us wall / 58.6us device, DRAM 74.1% (5.87TB/s).
// Same binary measured 63.68 / 63.97 / 65.73 / 64.77 us across four runs:
// +-1us run-to-run variance on the brokered chip (clock state / co-tenancy).
//
// Design:
//  - ~half the rows masked to zero (set_size ~ U[0,128]) -> skip the input
//    load for dead rows (read traffic 256MiB -> ~128MiB; 84us dense -> 64us).
//  - Blackwell 256-bit accesses: 2x v8.f32 per thread (64B/thread),
//    predicates first, loads batched, then stores.
//  - Warp = 32 consecutive 32B vectors = exactly one F=256 row ->
//    warp-uniform mask (no divergence); set_size is an L2-resident broadcast.
//
// Falsified alternatives (all at the same device-time floor): 1 f4/thr
// (73.8us), 4 f4/thr (64.0us), 8 f4/thr (65.8us), __ldcs/__stcs (neutral),
// persistent grid-stride (75.1us), 512-thr CTAs (64.3us), fronted
// zero-stores (64.0us). ~74% DRAM is the B300 ceiling for this
// half-dense-read + dense-write stream (read/write turnaround; pure dense
// stream measured 77%). Traffic floor: 256MiB writes (output poisoned,
// must be fully written) + ~128MiB expected reads.

#define N_DIM 128
#define SCALE 1.1f
#define V8_PER_THREAD 2
#define THREADS 256

// total float8 vectors = 32*64*128*(256/8) = 8,388,608
// f8 per row: 32 -> row = idx >> 5 ; n = row & 127 ; bt = row >> 7

__device__ __forceinline__ void ldg256_nc(const float* p, float v[8])
{
    asm volatile("ld.global.nc.v8.f32 {%0,%1,%2,%3,%4,%5,%6,%7}, [%8];"
                 : "=f"(v[0]), "=f"(v[1]), "=f"(v[2]), "=f"(v[3]),
                   "=f"(v[4]), "=f"(v[5]), "=f"(v[6]), "=f"(v[7])
                 : "l"(p));
}

__device__ __forceinline__ void stg256(float* p, const float v[8])
{
    asm volatile("st.global.v8.f32 [%0], {%1,%2,%3,%4,%5,%6,%7,%8};"
                 :: "l"(p),
                    "f"(v[0]), "f"(v[1]), "f"(v[2]), "f"(v[3]),
                    "f"(v[4]), "f"(v[5]), "f"(v[6]), "f"(v[7])
                 : "memory");
}

__global__ void __launch_bounds__(THREADS, 8)
er_mask_scale_kernel(const float* __restrict__ in,
                     const int* __restrict__ set_size,
                     float* __restrict__ out)
{
    // block handles 512 contiguous f8 (= 16 rows)
    unsigned base = blockIdx.x * (THREADS * V8_PER_THREAD) + threadIdx.x;

    bool live[V8_PER_THREAD];
    #pragma unroll
    for (int i = 0; i < V8_PER_THREAD; i++) {
        unsigned idx = base + i * THREADS;
        unsigned row = idx >> 5;              // (b,t,n)
        unsigned n   = row & (N_DIM - 1);
        unsigned bt  = row >> 7;
        int ss = __ldg(&set_size[bt]);        // L2-resident broadcast
        live[i] = ((int)n < ss);
    }

    float v[V8_PER_THREAD][8];
    #pragma unroll
    for (int i = 0; i < V8_PER_THREAD; i++) {
        #pragma unroll
        for (int j = 0; j < 8; j++) v[i][j] = 0.0f;
        if (live[i]) ldg256_nc(in + (size_t)(base + i * THREADS) * 8, v[i]);
    }

    #pragma unroll
    for (int i = 0; i < V8_PER_THREAD; i++) {
        if (live[i]) {
            #pragma unroll
            for (int j = 0; j < 8; j++) v[i][j] *= SCALE;
        }
        stg256(out + (size_t)(base + i * THREADS) * 8, v[i]);
    }
}

extern "C" void kernel_launch(void* const* d_in, const int* in_sizes, int n_in,
                              void* d_out, int out_size)
{
    const float* in = (const float*)d_in[0];
    const int* ss = (const int*)d_in[1];
    float* out = (float*)d_out;

    const unsigned total_f8 = 8388608u;
    const unsigned blocks = total_f8 / (THREADS * V8_PER_THREAD); // 16384

    er_mask_scale_kernel<<<blocks, THREADS>>>(in, ss, out);
}

// round 16
// speedup vs baseline: 1.0220x; 1.0220x over previous
#include <cuda_runtime.h>
#include <stdint.h>

// out[b,t,n,f] = in[b,t,n,f] * ((n < set_size[b,t]) ? (ALPHA+BETA) : 0)
// B=32, T=64, N=128, F=256, fp32.
//
// FINAL. Best measured 63.68us wall / 58.6us device, DRAM 74.1% (5.87TB/s).
// Same binary over five runs: 63.68 / 63.97 / 65.73 / 64.77 / 65.38 us —
// +-1us run-to-run variance on the brokered chip; device time stable at
// 58.6-59.4us = the HBM floor for this traffic mix.
//
// Design:
//  - ~half the rows masked to zero (set_size ~ U[0,128]) -> skip the input
//    load for dead rows (read traffic 256MiB -> ~128MiB; 84us dense -> 64us).
//  - Blackwell 256-bit accesses: 2x v8.f32 per thread (64B/thread),
//    predicates first, loads batched, then stores.
//  - Warp = 32 consecutive 32B vectors = exactly one F=256 row ->
//    warp-uniform mask (no divergence); set_size is an L2-resident broadcast.
//
// Falsified alternatives (all at the same device-time floor): 1 f4/thr
// (73.8us), 4 f4/thr (64.0us), 8 f4/thr (65.8us), __ldcs/__stcs (neutral),
// persistent grid-stride (75.1us), 512-thr CTAs (64.3us), fronted
// zero-stores (64.0us). ~74% DRAM is the B300 ceiling for this
// half-dense-read + dense-write stream (read/write turnaround; pure dense
// stream measured 77%). Traffic floor: 256MiB mandatory writes (output
// poisoned) + ~128MiB expected reads. memset+sparse-write would raise
// writes to 384MiB — strictly worse. TMA shares the same LTS cap — no gain.

#define N_DIM 128
#define SCALE 1.1f
#define V8_PER_THREAD 2
#define THREADS 256

// total float8 vectors = 32*64*128*(256/8) = 8,388,608
// f8 per row: 32 -> row = idx >> 5 ; n = row & 127 ; bt = row >> 7

__device__ __forceinline__ void ldg256_nc(const float* p, float v[8])
{
    asm volatile("ld.global.nc.v8.f32 {%0,%1,%2,%3,%4,%5,%6,%7}, [%8];"
                 : "=f"(v[0]), "=f"(v[1]), "=f"(v[2]), "=f"(v[3]),
                   "=f"(v[4]), "=f"(v[5]), "=f"(v[6]), "=f"(v[7])
                 : "l"(p));
}

__device__ __forceinline__ void stg256(float* p, const float v[8])
{
    asm volatile("st.global.v8.f32 [%0], {%1,%2,%3,%4,%5,%6,%7,%8};"
                 :: "l"(p),
                    "f"(v[0]), "f"(v[1]), "f"(v[2]), "f"(v[3]),
                    "f"(v[4]), "f"(v[5]), "f"(v[6]), "f"(v[7])
                 : "memory");
}

__global__ void __launch_bounds__(THREADS, 8)
er_mask_scale_kernel(const float* __restrict__ in,
                     const int* __restrict__ set_size,
                     float* __restrict__ out)
{
    // block handles 512 contiguous f8 (= 16 rows)
    unsigned base = blockIdx.x * (THREADS * V8_PER_THREAD) + threadIdx.x;

    bool live[V8_PER_THREAD];
    #pragma unroll
    for (int i = 0; i < V8_PER_THREAD; i++) {
        unsigned idx = base + i * THREADS;
        unsigned row = idx >> 5;              // (b,t,n)
        unsigned n   = row & (N_DIM - 1);
        unsigned bt  = row >> 7;
        int ss = __ldg(&set_size[bt]);        // L2-resident broadcast
        live[i] = ((int)n < ss);
    }

    float v[V8_PER_THREAD][8];
    #pragma unroll
    for (int i = 0; i < V8_PER_THREAD; i++) {
        #pragma unroll
        for (int j = 0; j < 8; j++) v[i][j] = 0.0f;
        if (live[i]) ldg256_nc(in + (size_t)(base + i * THREADS) * 8, v[i]);
    }

    #pragma unroll
    for (int i = 0; i < V8_PER_THREAD; i++) {
        if (live[i]) {
            #pragma unroll
            for (int j = 0; j < 8; j++) v[i][j] *= SCALE;
        }
        stg256(out + (size_t)(base + i * THREADS) * 8, v[i]);
    }
}

extern "C" void kernel_launch(void* const* d_in, const int* in_sizes, int n_in,
                              void* d_out, int out_size)
{
    const float* in = (const float*)d_in[0];
    const int* ss = (const int*)d_in[1];
    float* out = (float*)d_out;

    const unsigned total_f8 = 8388608u;
    const unsigned blocks = total_f8 / (THREADS * V8_PER_THREAD); // 16384

    er_mask_scale_kernel<<<blocks, THREADS>>>(in, ss, out);
}